// round 16
// baseline (speedup 1.0000x reference)
#include <cuda_runtime.h>
#include <cuda_fp16.h>
#include <math.h>
#include <stdint.h>

#define N_NODES 50000
#define NP      50176              // 392*128, 6272*8, 1024*49
#define N_EDGES 800000
#define EMBED_DIM 64
#define N_PROPS 3
#define FDIM 192
#define F3 576
#define NCLS2 100
#define STEP_MIN 2
#define STEP_MAX 6

// ---------------- device scratch (all GEMM operands fp16) ----------------
__device__ __half g_h16a[(size_t)NP * FDIM];
__device__ __half g_h16b[(size_t)NP * FDIM];
__device__ __half g_hs16[(size_t)NP * FDIM];
__device__ __half g_wc16 [(size_t)F3 * FDIM];
__device__ __half g_whr16[(size_t)F3 * FDIM];
__device__ __half g_cwr16[(size_t)NCLS2 * FDIM];
__device__ int    g_deg[NP];
__device__ int    g_rowp[NP + 1];
__device__ int    g_cursor[NP];
__device__ int    g_csr[N_EDGES];

// ================= setup: embed-gather + deg-zero + weight fold/round =================
__global__ void setup_kernel(const int* __restrict__ prop_ids,
                             const float* __restrict__ table,
                             const float* __restrict__ W_ih,
                             const float* __restrict__ W_edge,
                             const float* __restrict__ W_hh,
                             const float* __restrict__ conv_w) {
    int b = blockIdx.x;
    int j = threadIdx.x;
    if (b < NP) {
        float v = 0.f;
        if (b < N_NODES) {
            int p = j >> 6;
            int e = j & 63;
            int id = prop_ids[b * N_PROPS + p];
            v = table[(size_t)id * EMBED_DIM + e];
        }
        g_h16a[(size_t)b * FDIM + j] = __float2half_rn(v);
        if (j == 0) g_deg[b] = 0;
    } else if (b < NP + F3) {
        int i = b - NP;
        float s = 0.f;
        #pragma unroll 8
        for (int k = 0; k < FDIM; ++k)
            s = fmaf(__ldg(W_ih + i * FDIM + k), __ldg(W_edge + k * FDIM + j), s);
        g_wc16[(size_t)i * FDIM + j] = __float2half_rn(s);
    } else if (b < NP + 2 * F3) {
        int i = b - NP - F3;
        g_whr16[(size_t)i * FDIM + j] = __float2half_rn(__ldg(W_hh + (size_t)i * FDIM + j));
    } else {
        int i = b - NP - 2 * F3;
        g_cwr16[(size_t)i * FDIM + j] = __float2half_rn(__ldg(conv_w + (size_t)i * FDIM + j));
    }
}

// ================= CSR build =================
__global__ void csr_count_kernel(const int* __restrict__ dst) {
    int e = blockIdx.x * 256 + threadIdx.x;
    if (e < N_EDGES) atomicAdd(&g_deg[dst[e]], 1);
}
__global__ __launch_bounds__(1024) void scan_kernel() {
    __shared__ int part[1024];
    const int CH = 49;                 // 1024*49 = 50176 = NP
    int t = threadIdx.x;
    int base = t * CH;
    int s = 0;
    #pragma unroll 7
    for (int i = 0; i < CH; ++i) {
        int idx = base + i;
        if (idx < NP) s += g_deg[idx];
    }
    part[t] = s;
    __syncthreads();
    for (int off = 1; off < 1024; off <<= 1) {
        int v = part[t];
        int u = (t >= off) ? part[t - off] : 0;
        __syncthreads();
        part[t] = v + u;
        __syncthreads();
    }
    int run = (t > 0) ? part[t - 1] : 0;
    for (int i = 0; i < CH; ++i) {
        int idx = base + i;
        if (idx < NP) {
            g_rowp[idx]   = run;
            g_cursor[idx] = run;
            run += g_deg[idx];
        }
    }
    if (t == 0) g_rowp[NP] = N_EDGES;
}
__global__ void csr_fill_kernel(const int* __restrict__ src,
                                const int* __restrict__ dst) {
    int e = blockIdx.x * 256 + threadIdx.x;
    if (e < N_EDGES) {
        int p = atomicAdd(&g_cursor[dst[e]], 1);
        g_csr[p] = src[e];
    }
}

// ================= aggregation: hs16[n] = sum h16[src]  (fp32 acc, 4-edge MLP) =================
__global__ __launch_bounds__(192) void gather_kernel(const __half* __restrict__ h16) {
    int g = threadIdx.x / 24;
    int c = threadIdx.x % 24;          // uint4 (8 halves) index within row
    int n = blockIdx.x * 8 + g;
    int beg = __ldg(&g_rowp[n]);
    int end = __ldg(&g_rowp[n + 1]);
    const uint4* hp = reinterpret_cast<const uint4*>(h16);   // 24 uint4 per row
    float4 v0 = make_float4(0.f, 0.f, 0.f, 0.f);
    float4 v1 = make_float4(0.f, 0.f, 0.f, 0.f);

    #define ACC8(D) { \
        float2 t0 = __half22float2(*reinterpret_cast<__half2*>(&(D).x)); \
        float2 t1 = __half22float2(*reinterpret_cast<__half2*>(&(D).y)); \
        float2 t2 = __half22float2(*reinterpret_cast<__half2*>(&(D).z)); \
        float2 t3 = __half22float2(*reinterpret_cast<__half2*>(&(D).w)); \
        v0.x += t0.x; v0.y += t0.y; v0.z += t1.x; v0.w += t1.y; \
        v1.x += t2.x; v1.y += t2.y; v1.z += t3.x; v1.w += t3.y; }

    int i = beg;
    for (; i + 4 <= end; i += 4) {
        int s0 = __ldg(&g_csr[i]);
        int s1 = __ldg(&g_csr[i + 1]);
        int s2 = __ldg(&g_csr[i + 2]);
        int s3 = __ldg(&g_csr[i + 3]);
        uint4 d0 = hp[(size_t)s0 * 24 + c];
        uint4 d1 = hp[(size_t)s1 * 24 + c];
        uint4 d2 = hp[(size_t)s2 * 24 + c];
        uint4 d3 = hp[(size_t)s3 * 24 + c];
        ACC8(d0) ACC8(d1) ACC8(d2) ACC8(d3)
    }
    for (; i < end; ++i) {
        int s0 = __ldg(&g_csr[i]);
        uint4 d0 = hp[(size_t)s0 * 24 + c];
        ACC8(d0)
    }
    #undef ACC8

    __half2 o0 = __floats2half2_rn(v0.x, v0.y);
    __half2 o1 = __floats2half2_rn(v0.z, v0.w);
    __half2 o2 = __floats2half2_rn(v1.x, v1.y);
    __half2 o3 = __floats2half2_rn(v1.z, v1.w);
    uint4 o;
    o.x = *reinterpret_cast<uint32_t*>(&o0);
    o.y = *reinterpret_cast<uint32_t*>(&o1);
    o.z = *reinterpret_cast<uint32_t*>(&o2);
    o.w = *reinterpret_cast<uint32_t*>(&o3);
    reinterpret_cast<uint4*>(g_hs16)[(size_t)n * 24 + c] = o;
}

// ================= shared mma helpers =================
#define SAH 80

__device__ __forceinline__ void mma_f16(float* c, uint32_t a0, uint32_t a1,
                                        uint32_t a2, uint32_t a3,
                                        uint32_t b0, uint32_t b1) {
    asm volatile(
        "mma.sync.aligned.m16n8k16.row.col.f32.f16.f16.f32 "
        "{%0,%1,%2,%3}, {%4,%5,%6,%7}, {%8,%9}, {%0,%1,%2,%3};"
        : "+f"(c[0]), "+f"(c[1]), "+f"(c[2]), "+f"(c[3])
        : "r"(a0), "r"(a1), "r"(a2), "r"(a3), "r"(b0), "r"(b1));
}
__device__ __forceinline__ void cp16h(uint32_t saddr, const __half* g, int pred) {
    int sz = pred ? 16 : 0;
    asm volatile("cp.async.cg.shared.global [%0], [%1], 16, %2;"
                 :: "r"(saddr), "l"(g), "r"(sz) : "memory");
}
__device__ __forceinline__ float sigm(float x) { return 1.f / (1.f + expf(-x)); }

// ================= cls GEMM body (fp16 operands, K=192 = 3 slabs of 64) =================
#define CAST_B (128 * SAH * 2)
#define CBST_B (64 * SAH * 2)
#define CSTG_B (CAST_B + CBST_B)
#define CSMEM  (3 * CSTG_B)

__device__ __forceinline__ void cls_body(const __half* __restrict__ A,
                                         const __half* __restrict__ cwr,
                                         const float* __restrict__ conv_b,
                                         float* __restrict__ out, int ldc,
                                         int m0, int n0, __half* smh, uint32_t smb) {
    const int Ntot = NCLS2;
    int tid  = threadIdx.x;
    int lane = tid & 31, wid = tid >> 5;
    int wr = wid & 3, wc2 = wid >> 2;
    int lr = lane >> 2, lc = lane & 3;

    int a_row[4], a_c8[4], b_row[2], b_c8[2];
    #pragma unroll
    for (int i = 0; i < 4; ++i) { int it = i * 256 + tid; a_row[i] = it >> 3; a_c8[i] = it & 7; }
    #pragma unroll
    for (int i = 0; i < 2; ++i) { int it = i * 256 + tid; b_row[i] = it >> 3; b_c8[i] = it & 7; }

    #define CPREF(s) { \
        uint32_t sa_ = smb + ((s) % 3) * CSTG_B; \
        _Pragma("unroll") \
        for (int i = 0; i < 4; ++i) \
            cp16h(sa_ + (a_row[i] * SAH + a_c8[i] * 8) * 2, \
                  A + (size_t)(m0 + a_row[i]) * FDIM + (s) * 64 + a_c8[i] * 8, 1); \
        uint32_t sb_ = sa_ + CAST_B; \
        _Pragma("unroll") \
        for (int i = 0; i < 2; ++i) \
            cp16h(sb_ + (b_row[i] * SAH + b_c8[i] * 8) * 2, \
                  cwr + (size_t)(n0 + b_row[i]) * FDIM + (s) * 64 + b_c8[i] * 8, \
                  (n0 + b_row[i]) < Ntot); \
        asm volatile("cp.async.commit_group;" ::: "memory"); \
    }

    float acc[2][4][4];
    #pragma unroll
    for (int i = 0; i < 2; ++i)
        #pragma unroll
        for (int j = 0; j < 4; ++j)
            #pragma unroll
            for (int q = 0; q < 4; ++q) acc[i][j][q] = 0.f;

    CPREF(0);
    CPREF(1);

    #pragma unroll 1
    for (int s = 0; s < 3; ++s) {
        if (s + 2 < 3) { CPREF(s + 2); }
        else { asm volatile("cp.async.commit_group;" ::: "memory"); }
        asm volatile("cp.async.wait_group 2;" ::: "memory");
        __syncthreads();

        const __half* Asp = smh + (s % 3) * (CSTG_B / 2);
        const __half* Bsp = Asp + CAST_B / 2;
        #pragma unroll
        for (int ks = 0; ks < 4; ++ks) {
            int co = ks * 16 + 4 * lc;
            uint32_t a[2][4], b[4][2];
            #pragma unroll
            for (int ma = 0; ma < 2; ++ma) {
                int r = wr * 32 + ma * 16 + lr;
                uint2 lo = *reinterpret_cast<const uint2*>(Asp + r * SAH + co);
                uint2 hi = *reinterpret_cast<const uint2*>(Asp + (r + 8) * SAH + co);
                a[ma][0] = lo.x; a[ma][1] = hi.x; a[ma][2] = lo.y; a[ma][3] = hi.y;
            }
            #pragma unroll
            for (int na = 0; na < 4; ++na) {
                int bn = wc2 * 32 + na * 8 + lr;
                uint2 bb = *reinterpret_cast<const uint2*>(Bsp + bn * SAH + co);
                b[na][0] = bb.x; b[na][1] = bb.y;
            }
            #pragma unroll
            for (int ma = 0; ma < 2; ++ma)
                #pragma unroll
                for (int na = 0; na < 4; ++na)
                    mma_f16(acc[ma][na], a[ma][0], a[ma][1], a[ma][2], a[ma][3],
                            b[na][0], b[na][1]);
        }
        __syncthreads();
    }

    #pragma unroll
    for (int ma = 0; ma < 2; ++ma) {
        #pragma unroll
        for (int na = 0; na < 4; ++na) {
            int row = m0 + wr * 32 + ma * 16 + lr;
            int col = n0 + wc2 * 32 + na * 8 + lc * 2;
            #pragma unroll
            for (int half = 0; half < 2; ++half) {
                int r = row + half * 8;
                if (r >= N_NODES) continue;
                float v0 = acc[ma][na][half * 2 + 0];
                float v1 = acc[ma][na][half * 2 + 1];
                if (col + 1 < Ntot) {
                    v0 = sigm(v0 + __ldg(conv_b + col));
                    v1 = sigm(v1 + __ldg(conv_b + col + 1));
                    *reinterpret_cast<float2*>(out + (size_t)r * ldc + col) = make_float2(v0, v1);
                } else if (col < Ntot) {
                    v0 = sigm(v0 + __ldg(conv_b + col));
                    out[(size_t)r * ldc + col] = v0;
                }
            }
        }
    }
    #undef CPREF
}

// ================= FUSED GRU step kernel (fp16, 3-stage, + appended cls tiles) =================
// K = 384 concat = 6 slabs of 64 (3 over hs@wc, 3 over hold@whr).
#define FAST_B (128 * SAH * 2)
#define FBST_B (96 * SAH * 2)
#define FSTG_B (FAST_B + FBST_B)
#define FSMEM  (3 * FSTG_B)

__global__ __launch_bounds__(256)
void gru_fused_kernel(const __half* __restrict__ hs, const __half* __restrict__ hold,
                      const __half* __restrict__ wc, const __half* __restrict__ whr,
                      const float* __restrict__ b_ih, const float* __restrict__ b_hh,
                      __half* __restrict__ hnew16,
                      const __half* __restrict__ cwr, const float* __restrict__ conv_b,
                      float* __restrict__ out, int ldo) {
    extern __shared__ __half smh[];
    uint32_t smb;
    asm("{ .reg .u64 t; cvta.to.shared.u64 t, %1; cvt.u32.u64 %0, t; }"
        : "=r"(smb) : "l"(smh));

    if (blockIdx.x >= 6) {
        cls_body(hold, cwr, conv_b, out, ldo,
                 blockIdx.y * 128, (blockIdx.x - 6) * 64, smh, smb);
        return;
    }

    int tid  = threadIdx.x;
    int lane = tid & 31, wid = tid >> 5;
    int wr = wid & 3, wf = wid >> 2;
    int lr = lane >> 2, lc = lane & 3;
    int m0 = blockIdx.y * 128;
    int f0 = blockIdx.x * 32;

    int a_row[4], a_c8[4], b_row[3], b_c8[3];
    #pragma unroll
    for (int i = 0; i < 4; ++i) { int it = i * 256 + tid; a_row[i] = it >> 3; a_c8[i] = it & 7; }
    #pragma unroll
    for (int i = 0; i < 3; ++i) { int it = i * 256 + tid; b_row[i] = it >> 3; b_c8[i] = it & 7; }

    #define FPREF(s) { \
        const __half* Ap = (s) < 3 ? hs : hold; \
        const __half* Bp = (s) < 3 ? wc : whr; \
        int ko = ((s) < 3 ? (s) : (s) - 3) * 64; \
        uint32_t sa_ = smb + ((s) % 3) * FSTG_B; \
        _Pragma("unroll") \
        for (int i = 0; i < 4; ++i) \
            cp16h(sa_ + (a_row[i] * SAH + a_c8[i] * 8) * 2, \
                  Ap + (size_t)(m0 + a_row[i]) * FDIM + ko + a_c8[i] * 8, 1); \
        uint32_t sb_ = sa_ + FAST_B; \
        _Pragma("unroll") \
        for (int i = 0; i < 3; ++i) { \
            int q_ = b_row[i] >> 5; \
            int grow_ = q_ * FDIM + f0 + (b_row[i] & 31); \
            cp16h(sb_ + (b_row[i] * SAH + b_c8[i] * 8) * 2, \
                  Bp + (size_t)grow_ * FDIM + ko + b_c8[i] * 8, 1); \
        } \
        asm volatile("cp.async.commit_group;" ::: "memory"); \
    }

    float ar[2][2][4], az[2][2][4], ai[2][2][4], ah[2][2][4];
    #pragma unroll
    for (int i = 0; i < 2; ++i)
        #pragma unroll
        for (int j = 0; j < 2; ++j)
            #pragma unroll
            for (int q = 0; q < 4; ++q) {
                ar[i][j][q] = 0.f; az[i][j][q] = 0.f;
                ai[i][j][q] = 0.f; ah[i][j][q] = 0.f;
            }

    FPREF(0);
    FPREF(1);

    #pragma unroll 1
    for (int s = 0; s < 6; ++s) {
        if (s + 2 < 6) { FPREF(s + 2); }
        else { asm volatile("cp.async.commit_group;" ::: "memory"); }
        asm volatile("cp.async.wait_group 2;" ::: "memory");
        __syncthreads();

        const __half* Asp = smh + (s % 3) * (FSTG_B / 2);
        const __half* Bsp = Asp + FAST_B / 2;
        bool first = (s < 3);

        #pragma unroll
        for (int ks = 0; ks < 4; ++ks) {
            int co = ks * 16 + 4 * lc;
            uint32_t a[2][4], b[3][2][2];
            #pragma unroll
            for (int ma = 0; ma < 2; ++ma) {
                int r = wr * 32 + ma * 16 + lr;
                uint2 lo = *reinterpret_cast<const uint2*>(Asp + r * SAH + co);
                uint2 hi = *reinterpret_cast<const uint2*>(Asp + (r + 8) * SAH + co);
                a[ma][0] = lo.x; a[ma][1] = hi.x; a[ma][2] = lo.y; a[ma][3] = hi.y;
            }
            #pragma unroll
            for (int q = 0; q < 3; ++q)
                #pragma unroll
                for (int na = 0; na < 2; ++na) {
                    int bn = q * 32 + wf * 16 + na * 8 + lr;
                    uint2 bb = *reinterpret_cast<const uint2*>(Bsp + bn * SAH + co);
                    b[q][na][0] = bb.x; b[q][na][1] = bb.y;
                }
            #pragma unroll
            for (int ma = 0; ma < 2; ++ma)
                #pragma unroll
                for (int na = 0; na < 2; ++na) {
                    mma_f16(ar[ma][na], a[ma][0], a[ma][1], a[ma][2], a[ma][3],
                            b[0][na][0], b[0][na][1]);
                    mma_f16(az[ma][na], a[ma][0], a[ma][1], a[ma][2], a[ma][3],
                            b[1][na][0], b[1][na][1]);
                }
            if (first) {
                #pragma unroll
                for (int ma = 0; ma < 2; ++ma)
                    #pragma unroll
                    for (int na = 0; na < 2; ++na)
                        mma_f16(ai[ma][na], a[ma][0], a[ma][1], a[ma][2], a[ma][3],
                                b[2][na][0], b[2][na][1]);
            } else {
                #pragma unroll
                for (int ma = 0; ma < 2; ++ma)
                    #pragma unroll
                    for (int na = 0; na < 2; ++na)
                        mma_f16(ah[ma][na], a[ma][0], a[ma][1], a[ma][2], a[ma][3],
                                b[2][na][0], b[2][na][1]);
            }
        }
        __syncthreads();
    }

    // ---- gate epilogue: h_new in fp16 ----
    #pragma unroll
    for (int ma = 0; ma < 2; ++ma) {
        #pragma unroll
        for (int half = 0; half < 2; ++half) {
            int rr = m0 + wr * 32 + ma * 16 + half * 8 + lr;
            if (rr >= N_NODES) continue;
            #pragma unroll
            for (int na = 0; na < 2; ++na) {
                int c0 = f0 + wf * 16 + na * 8 + lc * 2;
                float2 ho = __half22float2(
                    *reinterpret_cast<const __half2*>(hold + (size_t)rr * FDIM + c0));
                float o[2];
                #pragma unroll
                for (int e = 0; e < 2; ++e) {
                    int c = c0 + e;
                    int q = half * 2 + e;
                    float sr = ar[ma][na][q] + __ldg(b_ih + c) + __ldg(b_hh + c);
                    float sz = az[ma][na][q] + __ldg(b_ih + FDIM + c) + __ldg(b_hh + FDIM + c);
                    float gn = ai[ma][na][q] + __ldg(b_ih + 2 * FDIM + c);
                    float hn = ah[ma][na][q] + __ldg(b_hh + 2 * FDIM + c);
                    float r_ = sigm(sr);
                    float z_ = sigm(sz);
                    float nn = tanhf(gn + r_ * hn);
                    float hv = e ? ho.y : ho.x;
                    o[e] = (1.f - z_) * nn + z_ * hv;
                }
                *reinterpret_cast<__half2*>(hnew16 + (size_t)rr * FDIM + c0) =
                    __floats2half2_rn(o[0], o[1]);
            }
        }
    }
    #undef FPREF
}

// ================= standalone cls GEMM (final step) =================
__global__ __launch_bounds__(256)
void cls_gemm_kernel(const __half* __restrict__ A, const __half* __restrict__ cwr,
                     const float* __restrict__ conv_b, float* __restrict__ out, int ldc) {
    extern __shared__ __half smh[];
    uint32_t smb;
    asm("{ .reg .u64 t; cvta.to.shared.u64 t, %1; cvt.u32.u64 %0, t; }"
        : "=r"(smb) : "l"(smh));
    cls_body(A, cwr, conv_b, out, ldc, blockIdx.y * 128, blockIdx.x * 64, smh, smb);
}

// ================= launch =================
extern "C" void kernel_launch(void* const* d_in, const int* in_sizes, int n_in,
                              void* d_out, int out_size) {
    const int*   prop_ids = (const int*)d_in[0];
    const int*   src      = (const int*)d_in[1];
    const int*   dst      = (const int*)d_in[2];
    const float* embed    = (const float*)d_in[3];
    const float* W_edge   = (const float*)d_in[4];
    const float* W_ih     = (const float*)d_in[5];
    const float* W_hh     = (const float*)d_in[6];
    const float* b_ih     = (const float*)d_in[7];
    const float* b_hh     = (const float*)d_in[8];
    const float* conv_w   = (const float*)d_in[9];
    const float* conv_b   = (const float*)d_in[10];
    float* out = (float*)d_out;

    __half *h16a, *h16b, *hs16, *wc16, *whr16, *cwr16;
    cudaGetSymbolAddress((void**)&h16a,  g_h16a);
    cudaGetSymbolAddress((void**)&h16b,  g_h16b);
    cudaGetSymbolAddress((void**)&hs16,  g_hs16);
    cudaGetSymbolAddress((void**)&wc16,  g_wc16);
    cudaGetSymbolAddress((void**)&whr16, g_whr16);
    cudaGetSymbolAddress((void**)&cwr16, g_cwr16);

    static int smem_set = 0;
    if (!smem_set) {
        cudaFuncSetAttribute(gru_fused_kernel,
                             cudaFuncAttributeMaxDynamicSharedMemorySize, FSMEM);
        cudaFuncSetAttribute(cls_gemm_kernel,
                             cudaFuncAttributeMaxDynamicSharedMemorySize, CSMEM);
        smem_set = 1;
    }

    const int MT = NP / 128;                       // 392
    const int ldo = (STEP_MAX - STEP_MIN + 1) * NCLS2;

    // ---- setup ----
    setup_kernel<<<NP + 2 * F3 + NCLS2, FDIM>>>(prop_ids, embed, W_ih, W_edge, W_hh, conv_w);
    csr_count_kernel<<<(N_EDGES + 255) / 256, 256>>>(dst);
    scan_kernel<<<1, 1024>>>();
    csr_fill_kernel<<<(N_EDGES + 255) / 256, 256>>>(src, dst);

    // ---- steps ----
    __half* bufs16[2] = {h16a, h16b};
    for (int step = 1; step <= STEP_MAX; ++step) {
        __half* hc16 = bufs16[(step - 1) & 1];
        __half* hn16 = bufs16[step & 1];
        gather_kernel<<<NP / 8, 192>>>(hc16);
        if (step - 1 >= STEP_MIN) {
            int s = step - 1 - STEP_MIN;
            gru_fused_kernel<<<dim3(8, MT, 1), 256, FSMEM>>>(
                hs16, hc16, wc16, whr16, b_ih, b_hh, hn16, cwr16, conv_b,
                out + s * NCLS2, ldo);
        } else {
            gru_fused_kernel<<<dim3(6, MT, 1), 256, FSMEM>>>(
                hs16, hc16, wc16, whr16, b_ih, b_hh, hn16, cwr16, conv_b,
                nullptr, ldo);
        }
    }
    // final cls on h_6
    {
        __half* hfin = bufs16[STEP_MAX & 1];
        int s = STEP_MAX - STEP_MIN;
        cls_gemm_kernel<<<dim3(2, MT, 1), 256, CSMEM>>>(hfin, cwr16, conv_b,
                                                        out + s * NCLS2, ldo);
    }
}

// round 17
// speedup vs baseline: 1.0213x; 1.0213x over previous
#include <cuda_runtime.h>
#include <cuda_fp16.h>
#include <math.h>
#include <stdint.h>

#define N_NODES 50000
#define NP      50176              // 392*128, 6272*8, 1024*49
#define N_EDGES 800000
#define EMBED_DIM 64
#define N_PROPS 3
#define FDIM 192
#define F3 576
#define NCLS2 100
#define STEP_MIN 2
#define STEP_MAX 6

// ---------------- device scratch (all GEMM operands fp16) ----------------
__device__ __half g_h16a[(size_t)NP * FDIM];
__device__ __half g_h16b[(size_t)NP * FDIM];
__device__ __half g_hs16[(size_t)NP * FDIM];
__device__ __half g_wc16 [(size_t)F3 * FDIM];
__device__ __half g_whr16[(size_t)F3 * FDIM];
__device__ __half g_cwr16[(size_t)NCLS2 * FDIM];
__device__ int    g_deg[NP];
__device__ int    g_rowp[NP + 1];
__device__ int    g_cursor[NP];
__device__ int    g_csr[N_EDGES];

// ================= setup: embed-gather + deg-zero + weight fold/round =================
__global__ void setup_kernel(const int* __restrict__ prop_ids,
                             const float* __restrict__ table,
                             const float* __restrict__ W_ih,
                             const float* __restrict__ W_edge,
                             const float* __restrict__ W_hh,
                             const float* __restrict__ conv_w) {
    int b = blockIdx.x;
    int j = threadIdx.x;
    if (b < NP) {
        float v = 0.f;
        if (b < N_NODES) {
            int p = j >> 6;
            int e = j & 63;
            int id = prop_ids[b * N_PROPS + p];
            v = table[(size_t)id * EMBED_DIM + e];
        }
        g_h16a[(size_t)b * FDIM + j] = __float2half_rn(v);
        if (j == 0) g_deg[b] = 0;
    } else if (b < NP + F3) {
        int i = b - NP;
        float s = 0.f;
        #pragma unroll 8
        for (int k = 0; k < FDIM; ++k)
            s = fmaf(__ldg(W_ih + i * FDIM + k), __ldg(W_edge + k * FDIM + j), s);
        g_wc16[(size_t)i * FDIM + j] = __float2half_rn(s);
    } else if (b < NP + 2 * F3) {
        int i = b - NP - F3;
        g_whr16[(size_t)i * FDIM + j] = __float2half_rn(__ldg(W_hh + (size_t)i * FDIM + j));
    } else {
        int i = b - NP - 2 * F3;
        g_cwr16[(size_t)i * FDIM + j] = __float2half_rn(__ldg(conv_w + (size_t)i * FDIM + j));
    }
}

// ================= CSR build =================
__global__ void csr_count_kernel(const int* __restrict__ dst) {
    int e = blockIdx.x * 256 + threadIdx.x;
    if (e < N_EDGES) atomicAdd(&g_deg[dst[e]], 1);
}
__global__ __launch_bounds__(1024) void scan_kernel() {
    __shared__ int part[1024];
    const int CH = 49;                 // 1024*49 = 50176 = NP
    int t = threadIdx.x;
    int base = t * CH;
    int s = 0;
    #pragma unroll 7
    for (int i = 0; i < CH; ++i) {
        int idx = base + i;
        if (idx < NP) s += g_deg[idx];
    }
    part[t] = s;
    __syncthreads();
    for (int off = 1; off < 1024; off <<= 1) {
        int v = part[t];
        int u = (t >= off) ? part[t - off] : 0;
        __syncthreads();
        part[t] = v + u;
        __syncthreads();
    }
    int run = (t > 0) ? part[t - 1] : 0;
    for (int i = 0; i < CH; ++i) {
        int idx = base + i;
        if (idx < NP) {
            g_rowp[idx]   = run;
            g_cursor[idx] = run;
            run += g_deg[idx];
        }
    }
    if (t == 0) g_rowp[NP] = N_EDGES;
}
__global__ void csr_fill_kernel(const int* __restrict__ src,
                                const int* __restrict__ dst) {
    int e = blockIdx.x * 256 + threadIdx.x;
    if (e < N_EDGES) {
        int p = atomicAdd(&g_cursor[dst[e]], 1);
        g_csr[p] = src[e];
    }
}

// ================= aggregation: hs16[n] = sum h16[src]  (fp32 acc, 4-edge MLP) =================
__global__ __launch_bounds__(192) void gather_kernel(const __half* __restrict__ h16) {
    int g = threadIdx.x / 24;
    int c = threadIdx.x % 24;          // uint4 (8 halves) index within row
    int n = blockIdx.x * 8 + g;
    int beg = __ldg(&g_rowp[n]);
    int end = __ldg(&g_rowp[n + 1]);
    const uint4* hp = reinterpret_cast<const uint4*>(h16);   // 24 uint4 per row
    float4 v0 = make_float4(0.f, 0.f, 0.f, 0.f);
    float4 v1 = make_float4(0.f, 0.f, 0.f, 0.f);

    #define ACC8(D) { \
        float2 t0 = __half22float2(*reinterpret_cast<__half2*>(&(D).x)); \
        float2 t1 = __half22float2(*reinterpret_cast<__half2*>(&(D).y)); \
        float2 t2 = __half22float2(*reinterpret_cast<__half2*>(&(D).z)); \
        float2 t3 = __half22float2(*reinterpret_cast<__half2*>(&(D).w)); \
        v0.x += t0.x; v0.y += t0.y; v0.z += t1.x; v0.w += t1.y; \
        v1.x += t2.x; v1.y += t2.y; v1.z += t3.x; v1.w += t3.y; }

    int i = beg;
    for (; i + 4 <= end; i += 4) {
        int s0 = __ldg(&g_csr[i]);
        int s1 = __ldg(&g_csr[i + 1]);
        int s2 = __ldg(&g_csr[i + 2]);
        int s3 = __ldg(&g_csr[i + 3]);
        uint4 d0 = hp[(size_t)s0 * 24 + c];
        uint4 d1 = hp[(size_t)s1 * 24 + c];
        uint4 d2 = hp[(size_t)s2 * 24 + c];
        uint4 d3 = hp[(size_t)s3 * 24 + c];
        ACC8(d0) ACC8(d1) ACC8(d2) ACC8(d3)
    }
    for (; i < end; ++i) {
        int s0 = __ldg(&g_csr[i]);
        uint4 d0 = hp[(size_t)s0 * 24 + c];
        ACC8(d0)
    }
    #undef ACC8

    __half2 o0 = __floats2half2_rn(v0.x, v0.y);
    __half2 o1 = __floats2half2_rn(v0.z, v0.w);
    __half2 o2 = __floats2half2_rn(v1.x, v1.y);
    __half2 o3 = __floats2half2_rn(v1.z, v1.w);
    uint4 o;
    o.x = *reinterpret_cast<uint32_t*>(&o0);
    o.y = *reinterpret_cast<uint32_t*>(&o1);
    o.z = *reinterpret_cast<uint32_t*>(&o2);
    o.w = *reinterpret_cast<uint32_t*>(&o3);
    reinterpret_cast<uint4*>(g_hs16)[(size_t)n * 24 + c] = o;
}

// ================= shared mma helpers =================
#define SAH 80

__device__ __forceinline__ void mma_f16(float* c, uint32_t a0, uint32_t a1,
                                        uint32_t a2, uint32_t a3,
                                        uint32_t b0, uint32_t b1) {
    asm volatile(
        "mma.sync.aligned.m16n8k16.row.col.f32.f16.f16.f32 "
        "{%0,%1,%2,%3}, {%4,%5,%6,%7}, {%8,%9}, {%0,%1,%2,%3};"
        : "+f"(c[0]), "+f"(c[1]), "+f"(c[2]), "+f"(c[3])
        : "r"(a0), "r"(a1), "r"(a2), "r"(a3), "r"(b0), "r"(b1));
}
__device__ __forceinline__ void cp16h(uint32_t saddr, const __half* g, int pred) {
    int sz = pred ? 16 : 0;
    asm volatile("cp.async.cg.shared.global [%0], [%1], 16, %2;"
                 :: "r"(saddr), "l"(g), "r"(sz) : "memory");
}
__device__ __forceinline__ float sigm(float x) { return 1.f / (1.f + expf(-x)); }

// ================= cls GEMM body (fp16 operands, K=192 = 3 slabs of 64) =================
#define CAST_B (128 * SAH * 2)
#define CBST_B (64 * SAH * 2)
#define CSTG_B (CAST_B + CBST_B)
#define CSMEM  (3 * CSTG_B)

__device__ __forceinline__ void cls_body(const __half* __restrict__ A,
                                         const __half* __restrict__ cwr,
                                         const float* __restrict__ conv_b,
                                         float* __restrict__ out, int ldc,
                                         int m0, int n0, __half* smh, uint32_t smb) {
    const int Ntot = NCLS2;
    int tid  = threadIdx.x;
    int lane = tid & 31, wid = tid >> 5;
    int wr = wid & 3, wc2 = wid >> 2;
    int lr = lane >> 2, lc = lane & 3;

    int a_row[4], a_c8[4], b_row[2], b_c8[2];
    #pragma unroll
    for (int i = 0; i < 4; ++i) { int it = i * 256 + tid; a_row[i] = it >> 3; a_c8[i] = it & 7; }
    #pragma unroll
    for (int i = 0; i < 2; ++i) { int it = i * 256 + tid; b_row[i] = it >> 3; b_c8[i] = it & 7; }

    #define CPREF(s) { \
        uint32_t sa_ = smb + ((s) % 3) * CSTG_B; \
        _Pragma("unroll") \
        for (int i = 0; i < 4; ++i) \
            cp16h(sa_ + (a_row[i] * SAH + a_c8[i] * 8) * 2, \
                  A + (size_t)(m0 + a_row[i]) * FDIM + (s) * 64 + a_c8[i] * 8, 1); \
        uint32_t sb_ = sa_ + CAST_B; \
        _Pragma("unroll") \
        for (int i = 0; i < 2; ++i) \
            cp16h(sb_ + (b_row[i] * SAH + b_c8[i] * 8) * 2, \
                  cwr + (size_t)(n0 + b_row[i]) * FDIM + (s) * 64 + b_c8[i] * 8, \
                  (n0 + b_row[i]) < Ntot); \
        asm volatile("cp.async.commit_group;" ::: "memory"); \
    }

    float acc[2][4][4];
    #pragma unroll
    for (int i = 0; i < 2; ++i)
        #pragma unroll
        for (int j = 0; j < 4; ++j)
            #pragma unroll
            for (int q = 0; q < 4; ++q) acc[i][j][q] = 0.f;

    CPREF(0);
    CPREF(1);

    #pragma unroll 1
    for (int s = 0; s < 3; ++s) {
        if (s + 2 < 3) { CPREF(s + 2); }
        else { asm volatile("cp.async.commit_group;" ::: "memory"); }
        asm volatile("cp.async.wait_group 2;" ::: "memory");
        __syncthreads();

        const __half* Asp = smh + (s % 3) * (CSTG_B / 2);
        const __half* Bsp = Asp + CAST_B / 2;
        #pragma unroll
        for (int ks = 0; ks < 4; ++ks) {
            int co = ks * 16 + 4 * lc;
            uint32_t a[2][4], b[4][2];
            #pragma unroll
            for (int ma = 0; ma < 2; ++ma) {
                int r = wr * 32 + ma * 16 + lr;
                uint2 lo = *reinterpret_cast<const uint2*>(Asp + r * SAH + co);
                uint2 hi = *reinterpret_cast<const uint2*>(Asp + (r + 8) * SAH + co);
                a[ma][0] = lo.x; a[ma][1] = hi.x; a[ma][2] = lo.y; a[ma][3] = hi.y;
            }
            #pragma unroll
            for (int na = 0; na < 4; ++na) {
                int bn = wc2 * 32 + na * 8 + lr;
                uint2 bb = *reinterpret_cast<const uint2*>(Bsp + bn * SAH + co);
                b[na][0] = bb.x; b[na][1] = bb.y;
            }
            #pragma unroll
            for (int ma = 0; ma < 2; ++ma)
                #pragma unroll
                for (int na = 0; na < 4; ++na)
                    mma_f16(acc[ma][na], a[ma][0], a[ma][1], a[ma][2], a[ma][3],
                            b[na][0], b[na][1]);
        }
        __syncthreads();
    }

    #pragma unroll
    for (int ma = 0; ma < 2; ++ma) {
        #pragma unroll
        for (int na = 0; na < 4; ++na) {
            int row = m0 + wr * 32 + ma * 16 + lr;
            int col = n0 + wc2 * 32 + na * 8 + lc * 2;
            #pragma unroll
            for (int half = 0; half < 2; ++half) {
                int r = row + half * 8;
                if (r >= N_NODES) continue;
                float v0 = acc[ma][na][half * 2 + 0];
                float v1 = acc[ma][na][half * 2 + 1];
                if (col + 1 < Ntot) {
                    v0 = sigm(v0 + __ldg(conv_b + col));
                    v1 = sigm(v1 + __ldg(conv_b + col + 1));
                    *reinterpret_cast<float2*>(out + (size_t)r * ldc + col) = make_float2(v0, v1);
                } else if (col < Ntot) {
                    v0 = sigm(v0 + __ldg(conv_b + col));
                    out[(size_t)r * ldc + col] = v0;
                }
            }
        }
    }
    #undef CPREF
}

// ================= FUSED GRU step kernel (fp16, 3-stage, + appended cls tiles) =================
// K = 384 concat = 6 slabs of 64 (3 over hs@wc, 3 over hold@whr).
// After the mainloop, stages 0/1/2 hold slabs 3/4/5 = the FULL hold tile
// (cols 0..191) -> epilogue reads hold from smem, no gmem re-read.
#define FAST_B (128 * SAH * 2)
#define FBST_B (96 * SAH * 2)
#define FSTG_B (FAST_B + FBST_B)
#define FSMEM  (3 * FSTG_B)

__global__ __launch_bounds__(256)
void gru_fused_kernel(const __half* __restrict__ hs, const __half* __restrict__ hold,
                      const __half* __restrict__ wc, const __half* __restrict__ whr,
                      const float* __restrict__ b_ih, const float* __restrict__ b_hh,
                      __half* __restrict__ hnew16,
                      const __half* __restrict__ cwr, const float* __restrict__ conv_b,
                      float* __restrict__ out, int ldo) {
    extern __shared__ __half smh[];
    uint32_t smb;
    asm("{ .reg .u64 t; cvta.to.shared.u64 t, %1; cvt.u32.u64 %0, t; }"
        : "=r"(smb) : "l"(smh));

    if (blockIdx.x >= 6) {
        cls_body(hold, cwr, conv_b, out, ldo,
                 blockIdx.y * 128, (blockIdx.x - 6) * 64, smh, smb);
        return;
    }

    int tid  = threadIdx.x;
    int lane = tid & 31, wid = tid >> 5;
    int wr = wid & 3, wf = wid >> 2;
    int lr = lane >> 2, lc = lane & 3;
    int m0 = blockIdx.y * 128;
    int f0 = blockIdx.x * 32;

    int a_row[4], a_c8[4], b_row[3], b_c8[3];
    #pragma unroll
    for (int i = 0; i < 4; ++i) { int it = i * 256 + tid; a_row[i] = it >> 3; a_c8[i] = it & 7; }
    #pragma unroll
    for (int i = 0; i < 3; ++i) { int it = i * 256 + tid; b_row[i] = it >> 3; b_c8[i] = it & 7; }

    #define FPREF(s) { \
        const __half* Ap = (s) < 3 ? hs : hold; \
        const __half* Bp = (s) < 3 ? wc : whr; \
        int ko = ((s) < 3 ? (s) : (s) - 3) * 64; \
        uint32_t sa_ = smb + ((s) % 3) * FSTG_B; \
        _Pragma("unroll") \
        for (int i = 0; i < 4; ++i) \
            cp16h(sa_ + (a_row[i] * SAH + a_c8[i] * 8) * 2, \
                  Ap + (size_t)(m0 + a_row[i]) * FDIM + ko + a_c8[i] * 8, 1); \
        uint32_t sb_ = sa_ + FAST_B; \
        _Pragma("unroll") \
        for (int i = 0; i < 3; ++i) { \
            int q_ = b_row[i] >> 5; \
            int grow_ = q_ * FDIM + f0 + (b_row[i] & 31); \
            cp16h(sb_ + (b_row[i] * SAH + b_c8[i] * 8) * 2, \
                  Bp + (size_t)grow_ * FDIM + ko + b_c8[i] * 8, 1); \
        } \
        asm volatile("cp.async.commit_group;" ::: "memory"); \
    }

    float ar[2][2][4], az[2][2][4], ai[2][2][4], ah[2][2][4];
    #pragma unroll
    for (int i = 0; i < 2; ++i)
        #pragma unroll
        for (int j = 0; j < 2; ++j)
            #pragma unroll
            for (int q = 0; q < 4; ++q) {
                ar[i][j][q] = 0.f; az[i][j][q] = 0.f;
                ai[i][j][q] = 0.f; ah[i][j][q] = 0.f;
            }

    FPREF(0);
    FPREF(1);

    #pragma unroll 1
    for (int s = 0; s < 6; ++s) {
        if (s + 2 < 6) { FPREF(s + 2); }
        else { asm volatile("cp.async.commit_group;" ::: "memory"); }
        asm volatile("cp.async.wait_group 2;" ::: "memory");
        __syncthreads();

        const __half* Asp = smh + (s % 3) * (FSTG_B / 2);
        const __half* Bsp = Asp + FAST_B / 2;
        bool first = (s < 3);

        #pragma unroll
        for (int ks = 0; ks < 4; ++ks) {
            int co = ks * 16 + 4 * lc;
            uint32_t a[2][4], b[3][2][2];
            #pragma unroll
            for (int ma = 0; ma < 2; ++ma) {
                int r = wr * 32 + ma * 16 + lr;
                uint2 lo = *reinterpret_cast<const uint2*>(Asp + r * SAH + co);
                uint2 hi = *reinterpret_cast<const uint2*>(Asp + (r + 8) * SAH + co);
                a[ma][0] = lo.x; a[ma][1] = hi.x; a[ma][2] = lo.y; a[ma][3] = hi.y;
            }
            #pragma unroll
            for (int q = 0; q < 3; ++q)
                #pragma unroll
                for (int na = 0; na < 2; ++na) {
                    int bn = q * 32 + wf * 16 + na * 8 + lr;
                    uint2 bb = *reinterpret_cast<const uint2*>(Bsp + bn * SAH + co);
                    b[q][na][0] = bb.x; b[q][na][1] = bb.y;
                }
            #pragma unroll
            for (int ma = 0; ma < 2; ++ma)
                #pragma unroll
                for (int na = 0; na < 2; ++na) {
                    mma_f16(ar[ma][na], a[ma][0], a[ma][1], a[ma][2], a[ma][3],
                            b[0][na][0], b[0][na][1]);
                    mma_f16(az[ma][na], a[ma][0], a[ma][1], a[ma][2], a[ma][3],
                            b[1][na][0], b[1][na][1]);
                }
            if (first) {
                #pragma unroll
                for (int ma = 0; ma < 2; ++ma)
                    #pragma unroll
                    for (int na = 0; na < 2; ++na)
                        mma_f16(ai[ma][na], a[ma][0], a[ma][1], a[ma][2], a[ma][3],
                                b[2][na][0], b[2][na][1]);
            } else {
                #pragma unroll
                for (int ma = 0; ma < 2; ++ma)
                    #pragma unroll
                    for (int na = 0; na < 2; ++na)
                        mma_f16(ah[ma][na], a[ma][0], a[ma][1], a[ma][2], a[ma][3],
                                b[2][na][0], b[2][na][1]);
            }
        }
        __syncthreads();
    }

    // ---- gate epilogue: hold read from persistent smem (slabs 3/4/5 in stages 0/1/2) ----
    #pragma unroll
    for (int ma = 0; ma < 2; ++ma) {
        #pragma unroll
        for (int half = 0; half < 2; ++half) {
            int rloc = wr * 32 + ma * 16 + half * 8 + lr;
            int rr = m0 + rloc;
            if (rr >= N_NODES) continue;
            #pragma unroll
            for (int na = 0; na < 2; ++na) {
                int c0 = f0 + wf * 16 + na * 8 + lc * 2;
                int stg = (3 + (c0 >> 6)) % 3;
                const __half* Ep = smh + stg * (FSTG_B / 2);
                float2 ho = __half22float2(
                    *reinterpret_cast<const __half2*>(Ep + rloc * SAH + (c0 & 63)));
                float o[2];
                #pragma unroll
                for (int e = 0; e < 2; ++e) {
                    int c = c0 + e;
                    int q = half * 2 + e;
                    float sr = ar[ma][na][q] + __ldg(b_ih + c) + __ldg(b_hh + c);
                    float sz = az[ma][na][q] + __ldg(b_ih + FDIM + c) + __ldg(b_hh + FDIM + c);
                    float gn = ai[ma][na][q] + __ldg(b_ih + 2 * FDIM + c);
                    float hn = ah[ma][na][q] + __ldg(b_hh + 2 * FDIM + c);
                    float r_ = sigm(sr);
                    float z_ = sigm(sz);
                    float nn = tanhf(gn + r_ * hn);
                    float hv = e ? ho.y : ho.x;
                    o[e] = (1.f - z_) * nn + z_ * hv;
                }
                *reinterpret_cast<__half2*>(hnew16 + (size_t)rr * FDIM + c0) =
                    __floats2half2_rn(o[0], o[1]);
            }
        }
    }
    #undef FPREF
}

// ================= standalone cls GEMM (final step) =================
__global__ __launch_bounds__(256)
void cls_gemm_kernel(const __half* __restrict__ A, const __half* __restrict__ cwr,
                     const float* __restrict__ conv_b, float* __restrict__ out, int ldc) {
    extern __shared__ __half smh[];
    uint32_t smb;
    asm("{ .reg .u64 t; cvta.to.shared.u64 t, %1; cvt.u32.u64 %0, t; }"
        : "=r"(smb) : "l"(smh));
    cls_body(A, cwr, conv_b, out, ldc, blockIdx.y * 128, blockIdx.x * 64, smh, smb);
}

// ================= launch =================
extern "C" void kernel_launch(void* const* d_in, const int* in_sizes, int n_in,
                              void* d_out, int out_size) {
    const int*   prop_ids = (const int*)d_in[0];
    const int*   src      = (const int*)d_in[1];
    const int*   dst      = (const int*)d_in[2];
    const float* embed    = (const float*)d_in[3];
    const float* W_edge   = (const float*)d_in[4];
    const float* W_ih     = (const float*)d_in[5];
    const float* W_hh     = (const float*)d_in[6];
    const float* b_ih     = (const float*)d_in[7];
    const float* b_hh     = (const float*)d_in[8];
    const float* conv_w   = (const float*)d_in[9];
    const float* conv_b   = (const float*)d_in[10];
    float* out = (float*)d_out;

    __half *h16a, *h16b, *hs16, *wc16, *whr16, *cwr16;
    cudaGetSymbolAddress((void**)&h16a,  g_h16a);
    cudaGetSymbolAddress((void**)&h16b,  g_h16b);
    cudaGetSymbolAddress((void**)&hs16,  g_hs16);
    cudaGetSymbolAddress((void**)&wc16,  g_wc16);
    cudaGetSymbolAddress((void**)&whr16, g_whr16);
    cudaGetSymbolAddress((void**)&cwr16, g_cwr16);

    static int smem_set = 0;
    if (!smem_set) {
        cudaFuncSetAttribute(gru_fused_kernel,
                             cudaFuncAttributeMaxDynamicSharedMemorySize, FSMEM);
        cudaFuncSetAttribute(cls_gemm_kernel,
                             cudaFuncAttributeMaxDynamicSharedMemorySize, CSMEM);
        smem_set = 1;
    }

    const int MT = NP / 128;                       // 392
    const int ldo = (STEP_MAX - STEP_MIN + 1) * NCLS2;

    // ---- setup ----
    setup_kernel<<<NP + 2 * F3 + NCLS2, FDIM>>>(prop_ids, embed, W_ih, W_edge, W_hh, conv_w);
    csr_count_kernel<<<(N_EDGES + 255) / 256, 256>>>(dst);
    scan_kernel<<<1, 1024>>>();
    csr_fill_kernel<<<(N_EDGES + 255) / 256, 256>>>(src, dst);

    // ---- steps ----
    __half* bufs16[2] = {h16a, h16b};
    for (int step = 1; step <= STEP_MAX; ++step) {
        __half* hc16 = bufs16[(step - 1) & 1];
        __half* hn16 = bufs16[step & 1];
        gather_kernel<<<NP / 8, 192>>>(hc16);
        if (step - 1 >= STEP_MIN) {
            int s = step - 1 - STEP_MIN;
            gru_fused_kernel<<<dim3(8, MT, 1), 256, FSMEM>>>(
                hs16, hc16, wc16, whr16, b_ih, b_hh, hn16, cwr16, conv_b,
                out + s * NCLS2, ldo);
        } else {
            gru_fused_kernel<<<dim3(6, MT, 1), 256, FSMEM>>>(
                hs16, hc16, wc16, whr16, b_ih, b_hh, hn16, cwr16, conv_b,
                nullptr, ldo);
        }
    }
    // final cls on h_6
    {
        __half* hfin = bufs16[STEP_MAX & 1];
        int s = STEP_MAX - STEP_MIN;
        cls_gemm_kernel<<<dim3(2, MT, 1), 256, CSMEM>>>(hfin, cwr16, conv_b,
                                                        out + s * NCLS2, ldo);
    }
}